// round 4
// baseline (speedup 1.0000x reference)
#include <cuda_runtime.h>
#include <cuda_bf16.h>
#include <cstdint>

// LSTM: B=8192, T=128, IN=32, H=64 (4H=256 gate rows), OUT=8.
// Inputs (metadata order): 0:x[B,T,32] 1:W_ih[256,32] 2:W_hh[256,64]
//                          3:b_ih[256] 4:b_hh[256] 5:W_fc[8,64] 6:b_fc[8]
// Output: [B,8] fp32.

#define B_TOT   8192
#define T_LEN   128
#define IN_SZ   32
#define HID     64
#define GATES   256     // 4*HID
#define WARPS   8
#define EPW     8       // batch elements per warp (4 f32x2 pairs)
#define CTA_E   (WARPS*EPW)   // 64 elements per CTA
#define NCTA    (B_TOT/CTA_E) // 128

typedef unsigned long long ull;

// Pre-transposed weights (prep kernel output). Layout (float index):
//   Wq[j*256 + (k>>2)*128 + l*4 + (k&3)] = W[(k*32+l)*RowLen + j]
// so lane l at column j loads two conflict-free float4s:
//   float4 idx j*64 + l  (k=0..3)  and  j*64 + 32 + l  (k=4..7)
__device__ float g_Whh[HID * GATES];   // 16384 floats
__device__ float g_Wih[IN_SZ * GATES]; //  8192 floats

// ---------------- packed f32x2 helpers ----------------
__device__ __forceinline__ ull pack2(float a, float b) {
    ull r;
    asm("mov.b64 %0, {%1, %2};" : "=l"(r) : "f"(a), "f"(b));
    return r;
}
__device__ __forceinline__ void unpack2(ull v, float& a, float& b) {
    asm("mov.b64 {%0, %1}, %2;" : "=f"(a), "=f"(b) : "l"(v));
}
__device__ __forceinline__ ull ffma2(ull a, ull b, ull c) {
    ull d;
    asm("fma.rn.f32x2 %0, %1, %2, %3;" : "=l"(d) : "l"(a), "l"(b), "l"(c));
    return d;
}

// ---------------- activations (high accuracy, MUFU-based) ----------------
__device__ __forceinline__ float sigmoidf_(float x) {
    float e = __expf(-x);                 // FMUL + MUFU.EX2
    return __fdividef(1.0f, 1.0f + e);    // MUFU.RCP
}
__device__ __forceinline__ float tanhf_(float x) {
    x = fminf(fmaxf(x, -15.0f), 15.0f);   // keep exp finite
    float e = __expf(-2.0f * x);
    float r = __fdividef(1.0f, 1.0f + e);
    return fmaf(-2.0f * e, r, 1.0f);      // (1-e)/(1+e), no cancellation blowup
}

// ---------------- weight prep ----------------
__global__ void lstm_prep_kernel(const float* __restrict__ W_ih,
                                 const float* __restrict__ W_hh) {
    int i = blockIdx.x * blockDim.x + threadIdx.x;  // 0..16383
    {
        int j = i >> 8;            // 0..63
        int r = i & 255;
        int khi = r >> 7;
        int low = r & 127;
        int l = low >> 2;
        int k = khi * 4 + (low & 3);
        g_Whh[i] = W_hh[(k * 32 + l) * HID + j];
    }
    if (i < IN_SZ * GATES) {
        int j = i >> 8;            // 0..31
        int r = i & 255;
        int khi = r >> 7;
        int low = r & 127;
        int l = low >> 2;
        int k = khi * 4 + (low & 3);
        g_Wih[i] = W_ih[(k * 32 + l) * IN_SZ + j];
    }
}

// one GEMM column: 8 dup'd weights x 4 element-pairs -> 32 FFMA2
__device__ __forceinline__ void gemm_col(ull acc[8][4], float4 wa, float4 wb,
                                         ull h0, ull h1, ull h2, ull h3) {
    ull hh[4] = {h0, h1, h2, h3};
    float wk[8] = {wa.x, wa.y, wa.z, wa.w, wb.x, wb.y, wb.z, wb.w};
#pragma unroll
    for (int k = 0; k < 8; k++) {
        ull wp = pack2(wk[k], wk[k]);
#pragma unroll
        for (int p = 0; p < 4; p++) acc[k][p] = ffma2(wp, hh[p], acc[k][p]);
    }
}

// ---------------- main LSTM kernel ----------------
__global__ __launch_bounds__(256, 1)
void lstm_main_kernel(const float* __restrict__ x,
                      const float* __restrict__ b_ih,
                      const float* __restrict__ b_hh,
                      const float* __restrict__ W_fc,
                      const float* __restrict__ b_fc,
                      float* __restrict__ out) {
    extern __shared__ float smem[];
    float* sWhh = smem;                       // 16384 floats (64 KB)
    float* sWih = smem + HID * GATES;         //  8192 floats (32 KB)
    ull*   h_all = (ull*)(smem + HID * GATES + IN_SZ * GATES);  // 8 warps * 256 ull
    ull*   x_all = h_all + WARPS * (HID * 4);                   // 8 warps * 128 ull

    // stage weights: global (prepped) -> shared
    {
        const float4* s0 = (const float4*)g_Whh;
        float4* d0 = (float4*)sWhh;
        for (int i = threadIdx.x; i < (HID * GATES) / 4; i += 256) d0[i] = s0[i];
        const float4* s1 = (const float4*)g_Wih;
        float4* d1 = (float4*)sWih;
        for (int i = threadIdx.x; i < (IN_SZ * GATES) / 4; i += 256) d1[i] = s1[i];
    }
    __syncthreads();

    const int w = threadIdx.x >> 5;
    const int l = threadIdx.x & 31;
    ull* hsm = h_all + w * (HID * 4);   // [64 j][4 pair] f32x2
    ull* xsm = x_all + w * (IN_SZ * 4); // [32 j][4 pair] f32x2
    const int ebase = blockIdx.x * CTA_E + w * EPW;

    // bias (b_ih + b_hh), one scalar per gate-row group k
    float bk[8];
#pragma unroll
    for (int k = 0; k < 8; k++) {
        int r = k * 32 + l;
        bk[k] = b_ih[r] + b_hh[r];
    }

    // state: c packed per (half, pair); h lives in hsm
    ull c[2][4];
#pragma unroll
    for (int hf = 0; hf < 2; hf++)
#pragma unroll
        for (int p = 0; p < 4; p++) c[hf][p] = 0ull;
    for (int i = l; i < HID * 4; i += 32) hsm[i] = 0ull;
    __syncwarp();

    const float* xb = x + (size_t)ebase * (T_LEN * IN_SZ) + l;
    float xv[EPW];
#pragma unroll
    for (int e = 0; e < EPW; e++) xv[e] = xb[e * (T_LEN * IN_SZ)];  // t=0

    const float4* Wh4 = (const float4*)sWhh;
    const float4* Wi4 = (const float4*)sWih;

    for (int t = 0; t < T_LEN; t++) {
        // stage x[:, t, :] into xsm (j=lane, pair=e>>1, comp=e&1)
        float* xsf = (float*)xsm;
#pragma unroll
        for (int e = 0; e < EPW; e++)
            xsf[l * 8 + (e >> 1) * 2 + (e & 1)] = xv[e];
        __syncwarp();

        // prefetch next timestep's x (latency hidden behind GEMMs)
        if (t < T_LEN - 1) {
#pragma unroll
            for (int e = 0; e < EPW; e++)
                xv[e] = xb[e * (T_LEN * IN_SZ) + (t + 1) * IN_SZ];
        }

        // init accumulators with bias (both halves of each pair)
        ull acc[8][4];
#pragma unroll
        for (int k = 0; k < 8; k++) {
            ull bp = pack2(bk[k], bk[k]);
#pragma unroll
            for (int p = 0; p < 4; p++) acc[k][p] = bp;
        }

        // input GEMM: j over 32 input features
#pragma unroll 4
        for (int j = 0; j < IN_SZ; j++) {
            ull h0 = xsm[j * 4 + 0], h1 = xsm[j * 4 + 1];
            ull h2 = xsm[j * 4 + 2], h3 = xsm[j * 4 + 3];
            float4 wa = Wi4[j * 64 + l];
            float4 wb = Wi4[j * 64 + 32 + l];
            gemm_col(acc, wa, wb, h0, h1, h2, h3);
        }

        // recurrent GEMM: j over 64 hidden units
#pragma unroll 4
        for (int j = 0; j < HID; j++) {
            ull h0 = hsm[j * 4 + 0], h1 = hsm[j * 4 + 1];
            ull h2 = hsm[j * 4 + 2], h3 = hsm[j * 4 + 3];
            float4 wa = Wh4[j * 64 + l];
            float4 wb = Wh4[j * 64 + 32 + l];
            gemm_col(acc, wa, wb, h0, h1, h2, h3);
        }
        __syncwarp();  // all lanes done reading hsm before owners overwrite

        // gates -> state update. Lane l owns hidden indices l (hf=0), l+32 (hf=1).
        // gate k mapping: i:k=hf, f:k=2+hf, g:k=4+hf, o:k=6+hf
#pragma unroll
        for (int hf = 0; hf < 2; hf++) {
#pragma unroll
            for (int p = 0; p < 4; p++) {
                float ia0, ia1, fa0, fa1, ga0, ga1, oa0, oa1, c0, c1;
                unpack2(acc[0 + hf][p], ia0, ia1);
                unpack2(acc[2 + hf][p], fa0, fa1);
                unpack2(acc[4 + hf][p], ga0, ga1);
                unpack2(acc[6 + hf][p], oa0, oa1);
                unpack2(c[hf][p], c0, c1);

                float I0 = sigmoidf_(ia0), F0 = sigmoidf_(fa0);
                float G0 = tanhf_(ga0),    O0 = sigmoidf_(oa0);
                c0 = fmaf(F0, c0, I0 * G0);
                float H0 = O0 * tanhf_(c0);

                float I1 = sigmoidf_(ia1), F1 = sigmoidf_(fa1);
                float G1 = tanhf_(ga1),    O1 = sigmoidf_(oa1);
                c1 = fmaf(F1, c1, I1 * G1);
                float H1 = O1 * tanhf_(c1);

                c[hf][p] = pack2(c0, c1);
                hsm[(l + 32 * hf) * 4 + p] = pack2(H0, H1);
            }
        }
        __syncwarp();  // publish h for next step
    }

    // final FC: out[e][o] = h[e] . W_fc[o] + b_fc[o]
    // 4 lanes per element, 2 outputs per lane
    {
        const float* hs = (const float*)hsm;
        int e = l >> 2;
        int o0 = (l & 3) * 2;
        float s0 = b_fc[o0], s1 = b_fc[o0 + 1];
        const int comp = (e >> 1) * 2 + (e & 1);
#pragma unroll 8
        for (int j = 0; j < HID; j++) {
            float hv = hs[j * 8 + comp];
            s0 = fmaf(hv, W_fc[o0 * HID + j], s0);
            s1 = fmaf(hv, W_fc[(o0 + 1) * HID + j], s1);
        }
        out[(size_t)(ebase + e) * 8 + o0]     = s0;
        out[(size_t)(ebase + e) * 8 + o0 + 1] = s1;
    }
}

extern "C" void kernel_launch(void* const* d_in, const int* in_sizes, int n_in,
                              void* d_out, int out_size) {
    const float* x    = (const float*)d_in[0];
    const float* W_ih = (const float*)d_in[1];
    const float* W_hh = (const float*)d_in[2];
    const float* b_ih = (const float*)d_in[3];
    const float* b_hh = (const float*)d_in[4];
    const float* W_fc = (const float*)d_in[5];
    const float* b_fc = (const float*)d_in[6];
    float* out = (float*)d_out;

    // dynamic smem: weights (96 KB) + h rings (16 KB) + x rings (8 KB)
    const int smem_bytes =
        (HID * GATES + IN_SZ * GATES) * 4 + WARPS * HID * 4 * 8 + WARPS * IN_SZ * 4 * 8;
    cudaFuncSetAttribute(lstm_main_kernel,
                         cudaFuncAttributeMaxDynamicSharedMemorySize, smem_bytes);

    lstm_prep_kernel<<<64, 256>>>(W_ih, W_hh);
    lstm_main_kernel<<<NCTA, 256, smem_bytes>>>(x, b_ih, b_hh, W_fc, b_fc, out);
}

// round 8
// speedup vs baseline: 1.0016x; 1.0016x over previous
#include <cuda_runtime.h>
#include <cuda_bf16.h>
#include <cstdint>

// LSTM: B=8192, T=128, IN=32, H=64 (4H=256 gate rows), OUT=8.
// Inputs (metadata order): 0:x[B,T,32] 1:W_ih[256,32] 2:W_hh[256,64]
//                          3:b_ih[256] 4:b_hh[256] 5:W_fc[8,64] 6:b_fc[8]
// Output: [B,8] fp32.

#define B_TOT   8192
#define T_LEN   128
#define IN_SZ   32
#define HID     64
#define GATES   256     // 4*HID
#define WARPS   8
#define EPW     8       // batch elements per warp (4 f32x2 pairs)
#define CTA_E   (WARPS*EPW)   // 64 elements per CTA
#define NCTA    (B_TOT/CTA_E) // 128

typedef unsigned long long ull;

// Pre-transposed weights (prep kernel output). Layout (float index):
//   Wq[j*256 + (k>>2)*128 + l*4 + (k&3)] = W[(k*32+l)*RowLen + j]
// so lane l at column j loads two conflict-free float4s:
//   float4 idx j*64 + l  (k=0..3)  and  j*64 + 32 + l  (k=4..7)
__device__ float g_Whh[HID * GATES];   // 16384 floats
__device__ float g_Wih[IN_SZ * GATES]; //  8192 floats

// ---------------- packed f32x2 helpers ----------------
__device__ __forceinline__ ull pack2(float a, float b) {
    ull r;
    asm("mov.b64 %0, {%1, %2};" : "=l"(r) : "f"(a), "f"(b));
    return r;
}
__device__ __forceinline__ void unpack2(ull v, float& a, float& b) {
    asm("mov.b64 {%0, %1}, %2;" : "=f"(a), "=f"(b) : "l"(v));
}
__device__ __forceinline__ ull ffma2(ull a, ull b, ull c) {
    ull d;
    asm("fma.rn.f32x2 %0, %1, %2, %3;" : "=l"(d) : "l"(a), "l"(b), "l"(c));
    return d;
}

// ---------------- activations (high accuracy, MUFU-based) ----------------
__device__ __forceinline__ float sigmoidf_(float x) {
    float e = __expf(-x);                 // FMUL + MUFU.EX2
    return __fdividef(1.0f, 1.0f + e);    // MUFU.RCP
}
__device__ __forceinline__ float tanhf_(float x) {
    x = fminf(fmaxf(x, -15.0f), 15.0f);   // keep exp finite
    float e = __expf(-2.0f * x);
    float r = __fdividef(1.0f, 1.0f + e);
    return fmaf(-2.0f * e, r, 1.0f);      // (1-e)/(1+e), no cancellation blowup
}

// ---------------- weight prep ----------------
__global__ void lstm_prep_kernel(const float* __restrict__ W_ih,
                                 const float* __restrict__ W_hh) {
    int i = blockIdx.x * blockDim.x + threadIdx.x;  // 0..16383
    {
        int j = i >> 8;            // 0..63
        int r = i & 255;
        int khi = r >> 7;
        int low = r & 127;
        int l = low >> 2;
        int k = khi * 4 + (low & 3);
        g_Whh[i] = W_hh[(k * 32 + l) * HID + j];
    }
    if (i < IN_SZ * GATES) {
        int j = i >> 8;            // 0..31
        int r = i & 255;
        int khi = r >> 7;
        int low = r & 127;
        int l = low >> 2;
        int k = khi * 4 + (low & 3);
        g_Wih[i] = W_ih[(k * 32 + l) * IN_SZ + j];
    }
}

// one GEMM column: 8 dup'd weights x 4 element-pairs -> 32 FFMA2
__device__ __forceinline__ void gemm_col(ull acc[8][4], float4 wa, float4 wb,
                                         ull h0, ull h1, ull h2, ull h3) {
    ull hh[4] = {h0, h1, h2, h3};
    float wk[8] = {wa.x, wa.y, wa.z, wa.w, wb.x, wb.y, wb.z, wb.w};
#pragma unroll
    for (int k = 0; k < 8; k++) {
        ull wp = pack2(wk[k], wk[k]);
#pragma unroll
        for (int p = 0; p < 4; p++) acc[k][p] = ffma2(wp, hh[p], acc[k][p]);
    }
}

// ---------------- main LSTM kernel ----------------
__global__ __launch_bounds__(256, 1)
void lstm_main_kernel(const float* __restrict__ x,
                      const float* __restrict__ b_ih,
                      const float* __restrict__ b_hh,
                      const float* __restrict__ W_fc,
                      const float* __restrict__ b_fc,
                      float* __restrict__ out) {
    extern __shared__ float smem[];
    float* sWhh = smem;                       // 16384 floats (64 KB)
    float* sWih = smem + HID * GATES;         //  8192 floats (32 KB)
    ull*   h_all = (ull*)(smem + HID * GATES + IN_SZ * GATES);  // 8 warps * 256 ull
    ull*   x_all = h_all + WARPS * (HID * 4);                   // 8 warps * 128 ull

    // stage weights: global (prepped) -> shared
    {
        const float4* s0 = (const float4*)g_Whh;
        float4* d0 = (float4*)sWhh;
        for (int i = threadIdx.x; i < (HID * GATES) / 4; i += 256) d0[i] = s0[i];
        const float4* s1 = (const float4*)g_Wih;
        float4* d1 = (float4*)sWih;
        for (int i = threadIdx.x; i < (IN_SZ * GATES) / 4; i += 256) d1[i] = s1[i];
    }
    __syncthreads();

    const int w = threadIdx.x >> 5;
    const int l = threadIdx.x & 31;
    ull* hsm = h_all + w * (HID * 4);   // [64 j][4 pair] f32x2
    ull* xsm = x_all + w * (IN_SZ * 4); // [32 j][4 pair] f32x2
    const int ebase = blockIdx.x * CTA_E + w * EPW;

    // bias (b_ih + b_hh), one scalar per gate-row group k
    float bk[8];
#pragma unroll
    for (int k = 0; k < 8; k++) {
        int r = k * 32 + l;
        bk[k] = b_ih[r] + b_hh[r];
    }

    // state: c packed per (half, pair); h lives in hsm
    ull c[2][4];
#pragma unroll
    for (int hf = 0; hf < 2; hf++)
#pragma unroll
        for (int p = 0; p < 4; p++) c[hf][p] = 0ull;
    for (int i = l; i < HID * 4; i += 32) hsm[i] = 0ull;
    __syncwarp();

    const float* xb = x + (size_t)ebase * (T_LEN * IN_SZ) + l;
    float xv[EPW];
#pragma unroll
    for (int e = 0; e < EPW; e++) xv[e] = xb[e * (T_LEN * IN_SZ)];  // t=0

    const float4* Wh4 = (const float4*)sWhh;
    const float4* Wi4 = (const float4*)sWih;

    for (int t = 0; t < T_LEN; t++) {
        // stage x[:, t, :] into xsm (j=lane, pair=e>>1, comp=e&1)
        float* xsf = (float*)xsm;
#pragma unroll
        for (int e = 0; e < EPW; e++)
            xsf[l * 8 + (e >> 1) * 2 + (e & 1)] = xv[e];
        __syncwarp();

        // prefetch next timestep's x (latency hidden behind GEMMs)
        if (t < T_LEN - 1) {
#pragma unroll
            for (int e = 0; e < EPW; e++)
                xv[e] = xb[e * (T_LEN * IN_SZ) + (t + 1) * IN_SZ];
        }

        // init accumulators with bias (both halves of each pair)
        ull acc[8][4];
#pragma unroll
        for (int k = 0; k < 8; k++) {
            ull bp = pack2(bk[k], bk[k]);
#pragma unroll
            for (int p = 0; p < 4; p++) acc[k][p] = bp;
        }

        // input GEMM: j over 32 input features
#pragma unroll 4
        for (int j = 0; j < IN_SZ; j++) {
            ull h0 = xsm[j * 4 + 0], h1 = xsm[j * 4 + 1];
            ull h2 = xsm[j * 4 + 2], h3 = xsm[j * 4 + 3];
            float4 wa = Wi4[j * 64 + l];
            float4 wb = Wi4[j * 64 + 32 + l];
            gemm_col(acc, wa, wb, h0, h1, h2, h3);
        }

        // recurrent GEMM: j over 64 hidden units
#pragma unroll 4
        for (int j = 0; j < HID; j++) {
            ull h0 = hsm[j * 4 + 0], h1 = hsm[j * 4 + 1];
            ull h2 = hsm[j * 4 + 2], h3 = hsm[j * 4 + 3];
            float4 wa = Wh4[j * 64 + l];
            float4 wb = Wh4[j * 64 + 32 + l];
            gemm_col(acc, wa, wb, h0, h1, h2, h3);
        }
        __syncwarp();  // all lanes done reading hsm before owners overwrite

        // gates -> state update. Lane l owns hidden indices l (hf=0), l+32 (hf=1).
        // gate k mapping: i:k=hf, f:k=2+hf, g:k=4+hf, o:k=6+hf
#pragma unroll
        for (int hf = 0; hf < 2; hf++) {
#pragma unroll
            for (int p = 0; p < 4; p++) {
                float ia0, ia1, fa0, fa1, ga0, ga1, oa0, oa1, c0, c1;
                unpack2(acc[0 + hf][p], ia0, ia1);
                unpack2(acc[2 + hf][p], fa0, fa1);
                unpack2(acc[4 + hf][p], ga0, ga1);
                unpack2(acc[6 + hf][p], oa0, oa1);
                unpack2(c[hf][p], c0, c1);

                float I0 = sigmoidf_(ia0), F0 = sigmoidf_(fa0);
                float G0 = tanhf_(ga0),    O0 = sigmoidf_(oa0);
                c0 = fmaf(F0, c0, I0 * G0);
                float H0 = O0 * tanhf_(c0);

                float I1 = sigmoidf_(ia1), F1 = sigmoidf_(fa1);
                float G1 = tanhf_(ga1),    O1 = sigmoidf_(oa1);
                c1 = fmaf(F1, c1, I1 * G1);
                float H1 = O1 * tanhf_(c1);

                c[hf][p] = pack2(c0, c1);
                hsm[(l + 32 * hf) * 4 + p] = pack2(H0, H1);
            }
        }
        __syncwarp();  // publish h for next step
    }

    // final FC: out[e][o] = h[e] . W_fc[o] + b_fc[o]
    // 4 lanes per element, 2 outputs per lane
    {
        const float* hs = (const float*)hsm;
        int e = l >> 2;
        int o0 = (l & 3) * 2;
        float s0 = b_fc[o0], s1 = b_fc[o0 + 1];
        const int comp = (e >> 1) * 2 + (e & 1);
#pragma unroll 8
        for (int j = 0; j < HID; j++) {
            float hv = hs[j * 8 + comp];
            s0 = fmaf(hv, W_fc[o0 * HID + j], s0);
            s1 = fmaf(hv, W_fc[(o0 + 1) * HID + j], s1);
        }
        out[(size_t)(ebase + e) * 8 + o0]     = s0;
        out[(size_t)(ebase + e) * 8 + o0 + 1] = s1;
    }
}

extern "C" void kernel_launch(void* const* d_in, const int* in_sizes, int n_in,
                              void* d_out, int out_size) {
    const float* x    = (const float*)d_in[0];
    const float* W_ih = (const float*)d_in[1];
    const float* W_hh = (const float*)d_in[2];
    const float* b_ih = (const float*)d_in[3];
    const float* b_hh = (const float*)d_in[4];
    const float* W_fc = (const float*)d_in[5];
    const float* b_fc = (const float*)d_in[6];
    float* out = (float*)d_out;

    // dynamic smem: weights (96 KB) + h rings (16 KB) + x rings (8 KB)
    const int smem_bytes =
        (HID * GATES + IN_SZ * GATES) * 4 + WARPS * HID * 4 * 8 + WARPS * IN_SZ * 4 * 8;
    cudaFuncSetAttribute(lstm_main_kernel,
                         cudaFuncAttributeMaxDynamicSharedMemorySize, smem_bytes);

    lstm_prep_kernel<<<64, 256>>>(W_ih, W_hh);
    lstm_main_kernel<<<NCTA, 256, smem_bytes>>>(x, b_ih, b_hh, W_fc, b_fc, out);
}

// round 17
// speedup vs baseline: 1.9105x; 1.9074x over previous
#include <cuda_runtime.h>
#include <cuda_bf16.h>
#include <cstdint>

// LSTM B=8192,T=128,IN=32,H=64(4H=256),OUT=8 via mma.sync (HMMA bf16, 3-pass hi/lo).
// Per CTA: 64 batch rows, 8 warps. Per step: D[64,256] = A[64,96]·W[256,96]^T,
// K layout [x 0-31 | h 32-95]. Gate permutation: D col n = gate (n&3) of hidden (n>>2).

#define T_LEN   128
#define MROWS   64
#define NCTA    128
#define KPITCH  104                 // bf16 per A/W row (conflict-free ldmatrix)
#define APITCH_B (KPITCH*2)         // 208 B
#define AVER_B  (MROWS*APITCH_B)    // 13312
#define WVER_B  (256*APITCH_B)      // 53248
#define DPITCH_F 260
#define DPITCH_B (DPITCH_F*4)       // 1040

#define OFF_A    0
#define OFF_W    (2*AVER_B)                    // 26624
#define OFF_D    (OFF_W + 2*WVER_B)            // 133120
#define OFF_BIAS (OFF_D + MROWS*DPITCH_B)      // 199680
#define OFF_WFC  (OFF_BIAS + 1024)             // 200704
#define OFF_BFC  (OFF_WFC + 2048)              // 202752
#define SMEM_SZ  (OFF_BFC + 32)                // 202784

// prepped weights: [ver hi/lo][n 256][k 104] bf16 (pad zeros), permuted bias
__device__ __nv_bfloat16 g_W[2][256][KPITCH];
__device__ float g_bias[256];

__device__ __forceinline__ uint32_t smem_u32(const void* p) {
    uint32_t a;
    asm("{ .reg .u64 t; cvta.to.shared.u64 t, %1; cvt.u32.u64 %0, t; }" : "=r"(a) : "l"(p));
    return a;
}
__device__ __forceinline__ void ldsm4(uint32_t addr, uint32_t* r) {
    asm volatile("ldmatrix.sync.aligned.m8n8.x4.shared.b16 {%0,%1,%2,%3}, [%4];"
                 : "=r"(r[0]), "=r"(r[1]), "=r"(r[2]), "=r"(r[3]) : "r"(addr));
}
__device__ __forceinline__ void mma16816(float* d, const uint32_t* a, const uint32_t* b) {
    asm volatile("mma.sync.aligned.m16n8k16.row.col.f32.bf16.bf16.f32 "
                 "{%0,%1,%2,%3}, {%4,%5,%6,%7}, {%8,%9}, {%0,%1,%2,%3};"
                 : "+f"(d[0]), "+f"(d[1]), "+f"(d[2]), "+f"(d[3])
                 : "r"(a[0]), "r"(a[1]), "r"(a[2]), "r"(a[3]), "r"(b[0]), "r"(b[1]));
}

__device__ __forceinline__ float sig_(float v) {
    float e = __expf(-v);
    return __fdividef(1.0f, 1.0f + e);
}
__device__ __forceinline__ float tanh_(float v) {
    v = fminf(fmaxf(v, -15.0f), 15.0f);
    float e = __expf(-2.0f * v);
    float r = __fdividef(1.0f, 1.0f + e);
    return fmaf(-2.0f * e, r, 1.0f);
}
__device__ __forceinline__ uint32_t packbf2(float a, float b) {
    return (uint32_t)__bfloat16_as_ushort(__float2bfloat16(a)) |
           ((uint32_t)__bfloat16_as_ushort(__float2bfloat16(b)) << 16);
}

// ---------------- weight prep ----------------
__global__ void prep_kernel(const float* __restrict__ W_ih, const float* __restrict__ W_hh,
                            const float* __restrict__ b_ih, const float* __restrict__ b_hh) {
    int idx = blockIdx.x * 256 + threadIdx.x;   // 96 blocks -> 24576
    int n = idx / 96, k = idx % 96;
    int r = (n & 3) * 64 + (n >> 2);
    float v = (k < 32) ? W_ih[r * 32 + k] : W_hh[r * 64 + (k - 32)];
    __nv_bfloat16 hi = __float2bfloat16(v);
    __nv_bfloat16 lo = __float2bfloat16(v - __bfloat162float(hi));
    g_W[0][n][k] = hi;
    g_W[1][n][k] = lo;
    if (idx < 256) {
        int rr = (idx & 3) * 64 + (idx >> 2);
        g_bias[idx] = b_ih[rr] + b_hh[rr];
    }
}

// ---------------- main kernel ----------------
__global__ __launch_bounds__(256, 1)
void lstm_hmma_kernel(const float* __restrict__ x, const float* __restrict__ W_fc,
                      const float* __restrict__ b_fc, float* __restrict__ out) {
    extern __shared__ char sm[];
    const uint32_t sb = smem_u32(sm);
    const int tid = threadIdx.x;
    const int w = tid >> 5, l = tid & 31;
    const int q = l & 3, g = l >> 2;
    const int blk = blockIdx.x;
    const int n0 = w * 32;

    // stage W/bias/fc; zero A
    {
        const float4* src = (const float4*)g_W;
        float4* dst = (float4*)(sm + OFF_W);
        for (int i = tid; i < (2 * WVER_B) / 16; i += 256) dst[i] = src[i];
        if (tid < 256) ((float*)(sm + OFF_BIAS))[tid] = g_bias[tid];
        for (int i = tid; i < 512; i += 256) ((float*)(sm + OFF_WFC))[i] = W_fc[i];
        if (tid < 8) ((float*)(sm + OFF_BFC))[tid] = b_fc[tid];
        uint32_t* za = (uint32_t*)(sm + OFF_A);
        for (int i = tid; i < (2 * AVER_B) / 4; i += 256) za[i] = 0;
    }
    __syncthreads();  // zeroing done before x staging below

    // x staging mapping: thread covers row m_x, cols qx*8..+7
    const int m_x = tid >> 2, qx = tid & 3;
    const float* xbase = x + ((size_t)(blk * MROWS + m_x) * T_LEN) * 32 + qx * 8;
    float xr[8];
#define LOAD_XR(ts) do {                                                           \
    const float4 v0 = *(const float4*)(xbase + (size_t)(ts) * 32);                 \
    const float4 v1 = *(const float4*)(xbase + (size_t)(ts) * 32 + 4);             \
    xr[0]=v0.x; xr[1]=v0.y; xr[2]=v0.z; xr[3]=v0.w;                                \
    xr[4]=v1.x; xr[5]=v1.y; xr[6]=v1.z; xr[7]=v1.w; } while (0)
#define STORE_XR() do {                                                            \
    char* ab = sm + OFF_A + m_x * APITCH_B + qx * 16;                              \
    _Pragma("unroll")                                                              \
    for (int i = 0; i < 8; i += 2) {                                               \
        float h0f = xr[i], h1f = xr[i + 1];                                        \
        __nv_bfloat16 bh0 = __float2bfloat16(h0f), bh1 = __float2bfloat16(h1f);    \
        *(uint32_t*)(ab + i * 2) =                                                 \
            (uint32_t)__bfloat16_as_ushort(bh0) |                                  \
            ((uint32_t)__bfloat16_as_ushort(bh1) << 16);                           \
        *(uint32_t*)(ab + AVER_B + i * 2) =                                        \
            packbf2(h0f - __bfloat162float(bh0), h1f - __bfloat162float(bh1));     \
    } } while (0)

    LOAD_XR(0);
    STORE_XR();
    LOAD_XR(1);
    __syncthreads();

    // bias regs (accumulator init values)
    float biasr[8];
    {
        const float* bs = (const float*)(sm + OFF_BIAS);
#pragma unroll
        for (int nt = 0; nt < 4; nt++) {
            biasr[nt * 2]     = bs[n0 + nt * 8 + 2 * q];
            biasr[nt * 2 + 1] = bs[n0 + nt * 8 + 2 * q + 1];
        }
    }

    // ldmatrix per-thread base offsets
    const uint32_t aoffH = sb + OFF_A + (uint32_t)(l & 15) * APITCH_B + ((l >> 4) * 16);
    const uint32_t aoffL = aoffH + AVER_B;
    const uint32_t boffH = sb + OFF_W + (uint32_t)n0 * APITCH_B +
                           (uint32_t)((l & 7) + ((l >> 4) << 3)) * APITCH_B +
                           (((l >> 3) & 1) * 16);
    const uint32_t boffL = boffH + WVER_B;

    // epilogue mapping: cell (row m_e, hidden jb+jj)
    const int m_e = tid & 63, jb = (tid >> 6) << 4;
    float c[16];
#pragma unroll
    for (int i = 0; i < 16; i++) c[i] = 0.0f;

    for (int t = 0; t < T_LEN; t++) {
        // ---------- GEMM ----------
        float acc[4][4][4];
#pragma unroll
        for (int mt = 0; mt < 4; mt++)
#pragma unroll
            for (int nt = 0; nt < 4; nt++) {
                acc[mt][nt][0] = biasr[nt * 2];
                acc[mt][nt][1] = biasr[nt * 2 + 1];
                acc[mt][nt][2] = biasr[nt * 2];
                acc[mt][nt][3] = biasr[nt * 2 + 1];
            }
#pragma unroll
        for (int kc = 0; kc < 6; kc++) {
            const uint32_t kb = kc * 32;
            uint32_t aH[4][4], bf0[4], bf1[4];
#pragma unroll
            for (int mt = 0; mt < 4; mt++) ldsm4(aoffH + mt * (16 * APITCH_B) + kb, aH[mt]);
            // W hi
            ldsm4(boffH + kb, bf0);
            ldsm4(boffH + 16 * APITCH_B + kb, bf1);
#pragma unroll
            for (int mt = 0; mt < 4; mt++) {
                mma16816(acc[mt][0], aH[mt], bf0);
                mma16816(acc[mt][1], aH[mt], bf0 + 2);
                mma16816(acc[mt][2], aH[mt], bf1);
                mma16816(acc[mt][3], aH[mt], bf1 + 2);
            }
            // A lo x W hi
            {
                uint32_t aL[4];
#pragma unroll
                for (int mt = 0; mt < 4; mt++) {
                    ldsm4(aoffL + mt * (16 * APITCH_B) + kb, aL);
                    mma16816(acc[mt][0], aL, bf0);
                    mma16816(acc[mt][1], aL, bf0 + 2);
                    mma16816(acc[mt][2], aL, bf1);
                    mma16816(acc[mt][3], aL, bf1 + 2);
                }
            }
            // A hi x W lo
            ldsm4(boffL + kb, bf0);
            ldsm4(boffL + 16 * APITCH_B + kb, bf1);
#pragma unroll
            for (int mt = 0; mt < 4; mt++) {
                mma16816(acc[mt][0], aH[mt], bf0);
                mma16816(acc[mt][1], aH[mt], bf0 + 2);
                mma16816(acc[mt][2], aH[mt], bf1);
                mma16816(acc[mt][3], aH[mt], bf1 + 2);
            }
        }
        // ---------- dump D to smem ----------
        {
            char* db = sm + OFF_D + (size_t)g * DPITCH_B + (n0 + 2 * q) * 4;
#pragma unroll
            for (int mt = 0; mt < 4; mt++)
#pragma unroll
                for (int nt = 0; nt < 4; nt++) {
                    char* p = db + mt * (16 * DPITCH_B) + nt * 32;
                    *(float2*)(p) = make_float2(acc[mt][nt][0], acc[mt][nt][1]);
                    *(float2*)(p + 8 * DPITCH_B) = make_float2(acc[mt][nt][2], acc[mt][nt][3]);
                }
        }
        __syncthreads();  // GEMM reads of A done; D visible

        // ---------- epilogue ----------
        if (t < T_LEN - 1) STORE_XR();  // x(t+1) into A cols 0-31
        {
            const float* drow = (const float*)(sm + OFF_D + (size_t)m_e * DPITCH_B);
            char* ha = sm + OFF_A + m_e * APITCH_B + (32 + jb) * 2;
#pragma unroll
            for (int jj = 0; jj < 16; jj += 2) {
                float4 g0 = *(const float4*)(drow + 4 * (jb + jj));
                float4 g1 = *(const float4*)(drow + 4 * (jb + jj + 1));
                float I0 = sig_(g0.x), F0 = sig_(g0.y), G0 = tanh_(g0.z), O0 = sig_(g0.w);
                float cc0 = fmaf(F0, c[jj], I0 * G0);
                c[jj] = cc0;
                float h0 = O0 * tanh_(cc0);
                float I1 = sig_(g1.x), F1 = sig_(g1.y), G1 = tanh_(g1.z), O1 = sig_(g1.w);
                float cc1 = fmaf(F1, c[jj + 1], I1 * G1);
                c[jj + 1] = cc1;
                float h1 = O1 * tanh_(cc1);

                __nv_bfloat16 bh0 = __float2bfloat16(h0), bh1 = __float2bfloat16(h1);
                *(uint32_t*)(ha + jj * 2) =
                    (uint32_t)__bfloat16_as_ushort(bh0) |
                    ((uint32_t)__bfloat16_as_ushort(bh1) << 16);
                *(uint32_t*)(ha + AVER_B + jj * 2) =
                    packbf2(h0 - __bfloat162float(bh0), h1 - __bfloat162float(bh1));
            }
        }
        if (t + 2 < T_LEN) LOAD_XR(t + 2);
        __syncthreads();  // h/x published before next GEMM
    }

    // ---------- final FC: out[m][o] = h.Wfc[o] + bfc[o] ----------
    {
        const float* wf = (const float*)(sm + OFF_WFC);
        const float* bf = (const float*)(sm + OFF_BFC);
        int m = tid >> 2, o2 = (tid & 3) * 2;
        float s0 = bf[o2], s1 = bf[o2 + 1];
        const char* ar = sm + OFF_A + m * APITCH_B + 64;  // col 32 -> byte 64
#pragma unroll 8
        for (int j = 0; j < 64; j++) {
            float hv = __bfloat162float(*(const __nv_bfloat16*)(ar + j * 2)) +
                       __bfloat162float(*(const __nv_bfloat16*)(ar + AVER_B + j * 2));
            s0 = fmaf(hv, wf[o2 * 64 + j], s0);
            s1 = fmaf(hv, wf[(o2 + 1) * 64 + j], s1);
        }
        out[(size_t)(blk * MROWS + m) * 8 + o2] = s0;
        out[(size_t)(blk * MROWS + m) * 8 + o2 + 1] = s1;
    }
}

extern "C" void kernel_launch(void* const* d_in, const int* in_sizes, int n_in,
                              void* d_out, int out_size) {
    const float* x    = (const float*)d_in[0];
    const float* W_ih = (const float*)d_in[1];
    const float* W_hh = (const float*)d_in[2];
    const float* b_ih = (const float*)d_in[3];
    const float* b_hh = (const float*)d_in[4];
    const float* W_fc = (const float*)d_in[5];
    const float* b_fc = (const float*)d_in[6];
    float* out = (float*)d_out;

    cudaFuncSetAttribute(lstm_hmma_kernel, cudaFuncAttributeMaxDynamicSharedMemorySize, SMEM_SZ);
    prep_kernel<<<96, 256>>>(W_ih, W_hh, b_ih, b_hh);
    lstm_hmma_kernel<<<NCTA, 256, SMEM_SZ>>>(x, W_fc, b_fc, out);
}